// round 10
// baseline (speedup 1.0000x reference)
#include <cuda_runtime.h>
#include <cstdint>
#include <math.h>

#define E_TOT 102400
#define NGRAPH 64
#define D_IN   1408
#define H1     512
#define H2     512
#define H3     256

// ---------------- scratch (__device__ globals; no allocs allowed) ----------
__device__ float g_Y1[(size_t)E_TOT * H1];
__device__ float g_Y2[(size_t)E_TOT * H2];
__device__ float g_W1T[(size_t)H1 * D_IN];   // WT, k-permuted per 8-group
__device__ float g_W2T[(size_t)H2 * H1];
__device__ float g_W3T[(size_t)H3 * H2];
__device__ int   g_gcum[NGRAPH + 1];

// k-permutation within each 8-group: stored order [0,4,1,5,2,6,3,7]
__host__ __device__ __forceinline__ int kperm(int k) {
    int l = k & 7;
    return (k & ~7) | ((l < 4) ? (2 * l) : (2 * l - 7));
}

// ---------------- helpers ---------------------------------------------------
#define CP_ASYNC16(dst, src) \
    asm volatile("cp.async.cg.shared.global [%0], [%1], 16;" :: "r"(dst), "l"(src) : "memory")
#define CP_COMMIT() asm volatile("cp.async.commit_group;" ::: "memory")
#define CP_WAIT(n)  asm volatile("cp.async.wait_group %0;" :: "n"(n) : "memory")

__device__ __forceinline__ uint32_t smem_u32(const void* p) {
    uint32_t a;
    asm("{ .reg .u64 t; cvta.to.shared.u64 t, %1; cvt.u32.u64 %0, t; }"
        : "=r"(a) : "l"(p));
    return a;
}

// m16n8k8 tf32 mma
__device__ __forceinline__ void mma_tf32(float* c, const uint32_t* a,
                                         uint32_t b0, uint32_t b1) {
    asm volatile(
        "mma.sync.aligned.m16n8k8.row.col.f32.tf32.tf32.f32 "
        "{%0,%1,%2,%3}, {%4,%5,%6,%7}, {%8,%9}, {%0,%1,%2,%3};"
        : "+f"(c[0]), "+f"(c[1]), "+f"(c[2]), "+f"(c[3])
        : "r"(a[0]), "r"(a[1]), "r"(a[2]), "r"(a[3]), "r"(b0), "r"(b1));
}

// ---------------- Kernel 0: prefix sum --------------------------------------
__global__ void k_prefix(const int* __restrict__ num) {
    if (threadIdx.x == 0) {
        int s = 0;
        g_gcum[0] = 0;
        for (int i = 0; i < NGRAPH; i++) { s += num[i]; g_gcum[i + 1] = s; }
    }
}

// ---------------- transpose + k-perm: dst[n][kperm(k)] = src[k][n] ----------
__global__ void __launch_bounds__(256) k_transpose(
    const float* __restrict__ src, float* __restrict__ dst, int R, int C)
{
    __shared__ float t[32][33];
    int bx = blockIdx.x * 32;  // n tile
    int by = blockIdx.y * 32;  // k tile
    int x = bx + threadIdx.x;
    #pragma unroll
    for (int i = 0; i < 32; i += 8)
        t[threadIdx.y + i][threadIdx.x] = src[(size_t)(by + threadIdx.y + i) * C + x];
    __syncthreads();
    int ko = kperm(by + threadIdx.x);
    #pragma unroll
    for (int i = 0; i < 32; i += 8)
        dst[(size_t)(bx + threadIdx.y + i) * R + ko] = t[threadIdx.x][threadIdx.y + i];
}

// ---------------- tiled tf32 GEMM: 4 warps, 64x64 warp tiles ----------------
// BM=128, BN=128, BK=32, 128 threads (2M x 2N warps).
// A smem: 128 rows x 36 words, UNpermuted, scalar LDS.32 frags (conflict-free).
// B smem: 128 n-rows x 40 words, k-PERMUTED content -> LDS.64 k-pairs
//         (conflict-free; WT in gmem is pre-permuted).
// MODE 0: A gathered (feat|nodes[ind]|gfeat); MODE 1: A dense [E][KDIM].
// EPI 0: relu(x+bias); EPI 1: sigmoid(x+bias). Y stored LINEAR.
template<int KDIM, int MODE, int EPI, int HOUT>
__global__ void __launch_bounds__(128) gemm_mma(
    const float* __restrict__ Af, const float* __restrict__ nodes,
    const float* __restrict__ gfeat, const int* __restrict__ ind,
    const float* __restrict__ WT, const float* __restrict__ bias,
    float* __restrict__ Yout)
{
    constexpr int BM = 128, BK = 32;
    constexpr int PA = 36, PB = 40;
    constexpr int STAGEF = BM * PA + 128 * PB;   // 9728 words
    constexpr int NC = KDIM / BK;

    extern __shared__ float sm[];

    const int tid  = threadIdx.x;
    const int lane = tid & 31;
    const int wid  = tid >> 5;          // 0..3
    const int warpM = wid & 1;
    const int warpN = wid >> 1;
    const int eBase = blockIdx.x * BM;
    const int nBase = blockIdx.y * 128;

    const int grp = lane >> 2;          // 0..7
    const int tig = lane & 3;           // 0..3

    float acc[4][8][4];
    #pragma unroll
    for (int i = 0; i < 4; i++)
        #pragma unroll
        for (int j = 0; j < 8; j++)
            #pragma unroll
            for (int u = 0; u < 4; u++) acc[i][j][u] = 0.f;

    // fragment word-offsets within a stage
    const int aOff = (warpM * 64 + grp) * PA + tig;                // + mi*16*PA (+8*PA) (+4)
    const int bOff = BM * PA + (warpN * 64 + grp) * PB + tig * 2;  // + ni*8*PB + ks*8

    // ---- chunk loader: thread owns one full A row and one full B row -------
    auto load_chunk = [&](int c) {
        float* As = sm + (c & 1) * STAGEF;
        float* Bs = As + BM * PA;
        const int k0 = c * BK;
        // A row = tid
        const float* asrc;
        if (MODE == 0) {
            const int e = eBase + tid;
            if (k0 < 256) {
                asrc = Af + (size_t)e * 256 + k0;
            } else if (k0 < 1280) {
                const int j   = (k0 - 256) >> 8;
                const int nid = __ldg(ind + e * 4 + j);
                asrc = nodes + (size_t)nid * 256 + ((k0 - 256) & 255);
            } else {
                int lo = 0, hi = NGRAPH;
                while (hi - lo > 1) {
                    int mid = (lo + hi) >> 1;
                    if (g_gcum[mid] <= eBase + tid) lo = mid; else hi = mid;
                }
                asrc = gfeat + (size_t)lo * 128 + (k0 - 1280);
            }
        } else {
            asrc = Af + (size_t)(eBase + tid) * KDIM + k0;
        }
        uint32_t adst = smem_u32(As + tid * PA);
        #pragma unroll
        for (int q = 0; q < 8; q++)
            CP_ASYNC16(adst + q * 16, asrc + q * 4);
        // B row = tid (WT row nBase+tid, content k-permuted in gmem)
        const float* bsrc = WT + (size_t)(nBase + tid) * KDIM + k0;
        uint32_t bdst = smem_u32(Bs + tid * PB);
        #pragma unroll
        for (int q = 0; q < 8; q++)
            CP_ASYNC16(bdst + q * 16, bsrc + q * 4);
        CP_COMMIT();
    };

    load_chunk(0);

    for (int c = 0; c < NC; c++) {
        if (c + 1 < NC) {
            load_chunk(c + 1);      // stage (c+1)&1, protected by trailing sync
            CP_WAIT(1);
        } else {
            CP_WAIT(0);
        }
        __syncthreads();

        const float* St = sm + (c & 1) * STAGEF;

        #pragma unroll
        for (int ks = 0; ks < 4; ks++) {
            // ---- A fragments: 4 m16-frags, scalar LDS.32 (conflict-free)
            uint32_t a[4][4];
            const float* Ab = St + aOff + ks * 8;
            #pragma unroll
            for (int mi = 0; mi < 4; mi++) {
                const int o = mi * 16 * PA;
                a[mi][0] = __float_as_uint(Ab[o]);
                a[mi][1] = __float_as_uint(Ab[o + 8 * PA]);
                a[mi][2] = __float_as_uint(Ab[o + 4]);
                a[mi][3] = __float_as_uint(Ab[o + 8 * PA + 4]);
            }
            // ---- B fragments: 8 LDS.64 k-pairs (conflict-free)
            const float* Bb = St + bOff + ks * 8;
            float2 b[8];
            #pragma unroll
            for (int ni = 0; ni < 8; ni++)
                b[ni] = *(const float2*)(Bb + ni * 8 * PB);
            // ---- 32 MMAs
            #pragma unroll
            for (int ni = 0; ni < 8; ni++) {
                const uint32_t b0 = __float_as_uint(b[ni].x);
                const uint32_t b1 = __float_as_uint(b[ni].y);
                #pragma unroll
                for (int mi = 0; mi < 4; mi++)
                    mma_tf32(acc[mi][ni], a[mi], b0, b1);
            }
        }
        __syncthreads();
    }

    // ---- epilogue: bias + activation -> Yout (linear, float2 stores) -------
    #pragma unroll
    for (int ni = 0; ni < 8; ni++) {
        const int col = nBase + warpN * 64 + ni * 8 + tig * 2;
        const float2 bb = *(const float2*)(bias + col);
        #pragma unroll
        for (int mi = 0; mi < 4; mi++) {
            const int e0 = eBase + warpM * 64 + mi * 16 + grp;
            #pragma unroll
            for (int h = 0; h < 2; h++) {
                float x0 = acc[mi][ni][h * 2 + 0] + bb.x;
                float x1 = acc[mi][ni][h * 2 + 1] + bb.y;
                float2 v;
                if (EPI == 0) {
                    v.x = fmaxf(x0, 0.f);
                    v.y = fmaxf(x1, 0.f);
                } else {
                    v.x = 1.f / (1.f + __expf(-x0));
                    v.y = 1.f / (1.f + __expf(-x1));
                }
                *(float2*)(Yout + (size_t)(e0 + h * 8) * HOUT + col) = v;
            }
        }
    }
}

// ---------------- LayerNorm over last dim (256) ------------------------------
__global__ void __launch_bounds__(256) k_ln(
    const float* __restrict__ H, const float* __restrict__ gamma,
    const float* __restrict__ beta, float* __restrict__ out)
{
    const int row  = blockIdx.x * 8 + (threadIdx.x >> 5);
    const int lane = threadIdx.x & 31;
    const float* hp = H + (size_t)row * 256 + lane * 8;
    float4 v0 = *(const float4*)(hp);
    float4 v1 = *(const float4*)(hp + 4);
    float s  = v0.x + v0.y + v0.z + v0.w + v1.x + v1.y + v1.z + v1.w;
    float sq = v0.x*v0.x + v0.y*v0.y + v0.z*v0.z + v0.w*v0.w
             + v1.x*v1.x + v1.y*v1.y + v1.z*v1.z + v1.w*v1.w;
    #pragma unroll
    for (int o = 16; o > 0; o >>= 1) {
        s  += __shfl_xor_sync(0xFFFFFFFFu, s,  o);
        sq += __shfl_xor_sync(0xFFFFFFFFu, sq, o);
    }
    const float mu  = s * (1.f / 256.f);
    const float var = sq * (1.f / 256.f) - mu * mu;
    const float rs  = rsqrtf(var + 1e-3f);
    const float4 g0 = *(const float4*)(gamma + lane * 8);
    const float4 g1 = *(const float4*)(gamma + lane * 8 + 4);
    const float4 b0 = *(const float4*)(beta + lane * 8);
    const float4 b1 = *(const float4*)(beta + lane * 8 + 4);
    float4 o0, o1;
    o0.x = g0.x * (v0.x - mu) * rs + b0.x;
    o0.y = g0.y * (v0.y - mu) * rs + b0.y;
    o0.z = g0.z * (v0.z - mu) * rs + b0.z;
    o0.w = g0.w * (v0.w - mu) * rs + b0.w;
    o1.x = g1.x * (v1.x - mu) * rs + b1.x;
    o1.y = g1.y * (v1.y - mu) * rs + b1.y;
    o1.z = g1.z * (v1.z - mu) * rs + b1.z;
    o1.w = g1.w * (v1.w - mu) * rs + b1.w;
    float* op = out + (size_t)row * 256 + lane * 8;
    *(float4*)(op)     = o0;
    *(float4*)(op + 4) = o1;
}

// ---------------------------------------------------------------------------
extern "C" void kernel_launch(void* const* d_in, const int* in_sizes, int n_in,
                              void* d_out, int out_size)
{
    const float* feat  = (const float*)d_in[0];
    const float* nodes = (const float*)d_in[1];
    const float* gfeat = (const float*)d_in[2];
    const int*   ind   = (const int*)  d_in[3];
    const int*   num   = (const int*)  d_in[4];
    const float* W1    = (const float*)d_in[5];
    const float* b1    = (const float*)d_in[6];
    const float* W2    = (const float*)d_in[7];
    const float* b2    = (const float*)d_in[8];
    const float* W3    = (const float*)d_in[9];
    const float* b3    = (const float*)d_in[10];
    const float* gamma = (const float*)d_in[11];
    const float* beta  = (const float*)d_in[12];
    float* out = (float*)d_out;

    const int SMEM_BYTES = 2 * (128 * 36 + 128 * 40) * 4;   // 77824 -> 2 CTAs/SM

    cudaFuncSetAttribute(gemm_mma<D_IN, 0, 0, H1>,
                         cudaFuncAttributeMaxDynamicSharedMemorySize, SMEM_BYTES);
    cudaFuncSetAttribute(gemm_mma<H1, 1, 0, H2>,
                         cudaFuncAttributeMaxDynamicSharedMemorySize, SMEM_BYTES);
    cudaFuncSetAttribute(gemm_mma<H2, 1, 1, H3>,
                         cudaFuncAttributeMaxDynamicSharedMemorySize, SMEM_BYTES);

    float* Y1;  cudaGetSymbolAddress((void**)&Y1,  g_Y1);
    float* Y2;  cudaGetSymbolAddress((void**)&Y2,  g_Y2);
    float* W1T; cudaGetSymbolAddress((void**)&W1T, g_W1T);
    float* W2T; cudaGetSymbolAddress((void**)&W2T, g_W2T);
    float* W3T; cudaGetSymbolAddress((void**)&W3T, g_W3T);

    k_prefix<<<1, 32>>>(num);

    dim3 tb(32, 8);
    k_transpose<<<dim3(H1 / 32, D_IN / 32), tb>>>(W1, W1T, D_IN, H1);
    k_transpose<<<dim3(H2 / 32, H1 / 32),   tb>>>(W2, W2T, H1, H2);
    k_transpose<<<dim3(H3 / 32, H2 / 32),   tb>>>(W3, W3T, H2, H3);

    gemm_mma<D_IN, 0, 0, H1><<<dim3(E_TOT / 128, H1 / 128), 128, SMEM_BYTES>>>(
        feat, nodes, gfeat, ind, W1T, b1, Y1);

    gemm_mma<H1, 1, 0, H2><<<dim3(E_TOT / 128, H2 / 128), 128, SMEM_BYTES>>>(
        Y1, nullptr, nullptr, nullptr, W2T, b2, Y2);

    gemm_mma<H2, 1, 1, H3><<<dim3(E_TOT / 128, H3 / 128), 128, SMEM_BYTES>>>(
        Y2, nullptr, nullptr, nullptr, W3T, b3, Y1);

    k_ln<<<E_TOT / 8, 256>>>(Y1, gamma, beta, out);
}

// round 11
// speedup vs baseline: 1.3832x; 1.3832x over previous
#include <cuda_runtime.h>
#include <cstdint>
#include <math.h>

#define E_TOT 102400
#define NGRAPH 64
#define D_IN   1408
#define H1     512
#define H2     512
#define H3     256

// ---------------- scratch (__device__ globals; no allocs allowed) ----------
__device__ float g_Y1[(size_t)E_TOT * H1];   // also holds sigmoid output for LN
__device__ float g_Y2[(size_t)E_TOT * H2];
__device__ int   g_gcum[NGRAPH + 1];

// ---------------- helpers ---------------------------------------------------
#define CP_ASYNC16(dst, src) \
    asm volatile("cp.async.cg.shared.global [%0], [%1], 16;" :: "r"(dst), "l"(src) : "memory")
#define CP_COMMIT() asm volatile("cp.async.commit_group;" ::: "memory")
#define CP_WAIT(n)  asm volatile("cp.async.wait_group %0;" :: "n"(n) : "memory")

__device__ __forceinline__ uint32_t smem_u32(const void* p) {
    uint32_t a;
    asm("{ .reg .u64 t; cvta.to.shared.u64 t, %1; cvt.u32.u64 %0, t; }"
        : "=r"(a) : "l"(p));
    return a;
}

// m16n8k8 tf32 mma: D(16x8,f32) += A(16x8,tf32) * B(8x8,tf32)
__device__ __forceinline__ void mma_tf32(float* c, const uint32_t* a,
                                         uint32_t b0, uint32_t b1) {
    asm volatile(
        "mma.sync.aligned.m16n8k8.row.col.f32.tf32.tf32.f32 "
        "{%0,%1,%2,%3}, {%4,%5,%6,%7}, {%8,%9}, {%0,%1,%2,%3};"
        : "+f"(c[0]), "+f"(c[1]), "+f"(c[2]), "+f"(c[3])
        : "r"(a[0]), "r"(a[1]), "r"(a[2]), "r"(a[3]), "r"(b0), "r"(b1));
}

// ---------------- Kernel 0: prefix sum of num -------------------------------
__global__ void k_prefix(const int* __restrict__ num) {
    if (threadIdx.x == 0) {
        int s = 0;
        g_gcum[0] = 0;
        for (int i = 0; i < NGRAPH; i++) { s += num[i]; g_gcum[i + 1] = s; }
    }
}

// ---------------- tiled tf32 GEMM -------------------------------------------
// Identical to the 1883us R4 kernel except: 3 cp.async stages (2-chunk
// lookahead) and ONE __syncthreads per chunk.
// Tile: BM=128, BN=128, BK=32. 256 threads = 8 warps (4M x 2N), warp 32x64.
// A smem: 128 rows x 36 words; B smem: 32 k-rows x 136 words. Conflict-free.
// MODE 0: A gathered (feat | nodes[ind] | gfeat);  MODE 1: A dense [E][KDIM].
// EPI  0: relu(x + bias);  EPI 1: sigmoid(x + bias).  Output: Yout[E][HOUT].
template<int KDIM, int MODE, int EPI, int HOUT>
__global__ void __launch_bounds__(256) gemm_mma(
    const float* __restrict__ Af, const float* __restrict__ nodes,
    const float* __restrict__ gfeat, const int* __restrict__ ind,
    const float* __restrict__ W, const float* __restrict__ bias,
    float* __restrict__ Yout)
{
    constexpr int BM = 128, BN = 128, BK = 32;
    constexpr int PA = 36;    // A smem row stride (floats)
    constexpr int PB = 136;   // B smem row stride (floats)
    constexpr int STAGEF = BM * PA + BK * PB;        // 8960 floats / stage
    constexpr int NC = KDIM / BK;

    extern __shared__ float sm[];

    const int tid  = threadIdx.x;
    const int wid  = tid >> 5;
    const int lane = tid & 31;
    const int warpM = wid & 3;       // 0..3
    const int warpN = wid >> 2;      // 0..1
    const int eBase = blockIdx.x * BM;
    const int nBase = blockIdx.y * BN;

    const int grp = lane >> 2;       // 0..7
    const int tig = lane & 3;        // 0..3

    float acc[2][8][4];
    #pragma unroll
    for (int i = 0; i < 2; i++)
        #pragma unroll
        for (int j = 0; j < 8; j++)
            #pragma unroll
            for (int u = 0; u < 4; u++) acc[i][j][u] = 0.f;

    // ---- chunk loader ------------------------------------------------------
    const int arow  = tid >> 1;
    const int ahalf = (tid & 1) * 16;

    auto load_chunk = [&](int c) {
        float* As = sm + (c % 3) * STAGEF;
        float* Bs = As + BM * PA;
        const int k0 = c * BK;
        // ---- A
        const float* asrc;
        if (MODE == 0) {
            const int e = eBase + arow;
            const int k = k0 + ahalf;
            if (k < 256) {
                asrc = Af + (size_t)e * 256 + k;
            } else if (k < 1280) {
                const int j   = (k - 256) >> 8;
                const int nid = __ldg(ind + e * 4 + j);
                asrc = nodes + (size_t)nid * 256 + ((k - 256) & 255);
            } else {
                int lo = 0, hi = NGRAPH;
                while (hi - lo > 1) {
                    int mid = (lo + hi) >> 1;
                    if (g_gcum[mid] <= e) lo = mid; else hi = mid;
                }
                asrc = gfeat + (size_t)lo * 128 + (k - 1280);
            }
        } else {
            asrc = Af + (size_t)(eBase + arow) * KDIM + k0 + ahalf;
        }
        uint32_t adst = smem_u32(As + arow * PA + ahalf);
        #pragma unroll
        for (int q = 0; q < 4; q++)
            CP_ASYNC16(adst + q * 16, asrc + q * 4);
        // ---- B (row-major W [k][n])
        #pragma unroll
        for (int i = 0; i < 4; i++) {
            const int idx  = tid + 256 * i;
            const int krow = idx >> 5;
            const int col4 = idx & 31;
            const float* bsrc = W + (size_t)(k0 + krow) * HOUT + nBase + col4 * 4;
            uint32_t bdst = smem_u32(Bs + krow * PB + col4 * 4);
            CP_ASYNC16(bdst, bsrc);
        }
        CP_COMMIT();
    };

    // ---- prologue: 2 chunks in flight --------------------------------------
    load_chunk(0);
    if (NC > 1) load_chunk(1);

    for (int c = 0; c < NC; c++) {
        if (c + 1 < NC) CP_WAIT(1); else CP_WAIT(0);   // chunk c landed
        __syncthreads();                                // all warps past compute(c-1)
        if (c + 2 < NC) load_chunk(c + 2);              // stage (c-1)%3: safe after sync

        const uint32_t* As = (const uint32_t*)(sm + (c % 3) * STAGEF);
        const uint32_t* Bs = As + BM * PA;

        #pragma unroll
        for (int ks = 0; ks < 4; ks++) {
            const int kb = ks * 8;
            uint32_t a[2][4];
            #pragma unroll
            for (int mi = 0; mi < 2; mi++) {
                const int m = warpM * 32 + mi * 16 + grp;
                const int k = kb + tig;
                a[mi][0] = As[m * PA + k];
                a[mi][1] = As[(m + 8) * PA + k];
                a[mi][2] = As[m * PA + k + 4];
                a[mi][3] = As[(m + 8) * PA + k + 4];
            }
            #pragma unroll
            for (int ni = 0; ni < 8; ni++) {
                const int n = warpN * 64 + ni * 8 + grp;
                const uint32_t b0 = Bs[(kb + tig) * PB + n];
                const uint32_t b1 = Bs[(kb + tig + 4) * PB + n];
                mma_tf32(acc[0][ni], a[0], b0, b1);
                mma_tf32(acc[1][ni], a[1], b0, b1);
            }
        }
    }

    // ---- epilogue: bias + activation -> Yout ------------------------------
    #pragma unroll
    for (int ni = 0; ni < 8; ni++) {
        const int col = nBase + warpN * 64 + ni * 8 + tig * 2;
        const float2 bb = *(const float2*)(bias + col);
        #pragma unroll
        for (int mi = 0; mi < 2; mi++) {
            const int e0 = eBase + warpM * 32 + mi * 16 + grp;
            #pragma unroll
            for (int h = 0; h < 2; h++) {       // rows e0, e0+8
                float x0 = acc[mi][ni][h * 2 + 0] + bb.x;
                float x1 = acc[mi][ni][h * 2 + 1] + bb.y;
                float2 v;
                if (EPI == 0) {
                    v.x = fmaxf(x0, 0.f);
                    v.y = fmaxf(x1, 0.f);
                } else {
                    v.x = 1.f / (1.f + __expf(-x0));
                    v.y = 1.f / (1.f + __expf(-x1));
                }
                *(float2*)(Yout + (size_t)(e0 + h * 8) * HOUT + col) = v;
            }
        }
    }
}

// ---------------- LayerNorm over last dim (256) ------------------------------
__global__ void __launch_bounds__(256) k_ln(
    const float* __restrict__ H, const float* __restrict__ gamma,
    const float* __restrict__ beta, float* __restrict__ out)
{
    const int row  = blockIdx.x * 8 + (threadIdx.x >> 5);
    const int lane = threadIdx.x & 31;
    const float* hp = H + (size_t)row * 256 + lane * 8;
    float4 v0 = *(const float4*)(hp);
    float4 v1 = *(const float4*)(hp + 4);
    float s  = v0.x + v0.y + v0.z + v0.w + v1.x + v1.y + v1.z + v1.w;
    float sq = v0.x*v0.x + v0.y*v0.y + v0.z*v0.z + v0.w*v0.w
             + v1.x*v1.x + v1.y*v1.y + v1.z*v1.z + v1.w*v1.w;
    #pragma unroll
    for (int o = 16; o > 0; o >>= 1) {
        s  += __shfl_xor_sync(0xFFFFFFFFu, s,  o);
        sq += __shfl_xor_sync(0xFFFFFFFFu, sq, o);
    }
    const float mu  = s * (1.f / 256.f);
    const float var = sq * (1.f / 256.f) - mu * mu;
    const float rs  = rsqrtf(var + 1e-3f);
    const float4 g0 = *(const float4*)(gamma + lane * 8);
    const float4 g1 = *(const float4*)(gamma + lane * 8 + 4);
    const float4 b0 = *(const float4*)(beta + lane * 8);
    const float4 b1 = *(const float4*)(beta + lane * 8 + 4);
    float4 o0, o1;
    o0.x = g0.x * (v0.x - mu) * rs + b0.x;
    o0.y = g0.y * (v0.y - mu) * rs + b0.y;
    o0.z = g0.z * (v0.z - mu) * rs + b0.z;
    o0.w = g0.w * (v0.w - mu) * rs + b0.w;
    o1.x = g1.x * (v1.x - mu) * rs + b1.x;
    o1.y = g1.y * (v1.y - mu) * rs + b1.y;
    o1.z = g1.z * (v1.z - mu) * rs + b1.z;
    o1.w = g1.w * (v1.w - mu) * rs + b1.w;
    float* op = out + (size_t)row * 256 + lane * 8;
    *(float4*)(op)     = o0;
    *(float4*)(op + 4) = o1;
}

// ---------------------------------------------------------------------------
extern "C" void kernel_launch(void* const* d_in, const int* in_sizes, int n_in,
                              void* d_out, int out_size)
{
    const float* feat  = (const float*)d_in[0];
    const float* nodes = (const float*)d_in[1];
    const float* gfeat = (const float*)d_in[2];
    const int*   ind   = (const int*)  d_in[3];
    const int*   num   = (const int*)  d_in[4];
    const float* W1    = (const float*)d_in[5];
    const float* b1    = (const float*)d_in[6];
    const float* W2    = (const float*)d_in[7];
    const float* b2    = (const float*)d_in[8];
    const float* W3    = (const float*)d_in[9];
    const float* b3    = (const float*)d_in[10];
    const float* gamma = (const float*)d_in[11];
    const float* beta  = (const float*)d_in[12];
    float* out = (float*)d_out;

    constexpr int PA = 36, PB = 136;
    const int SMEM_BYTES = 3 * (128 * PA + 32 * PB) * 4;   // 107520 -> 2 CTAs/SM (215KB)

    cudaFuncSetAttribute(gemm_mma<D_IN, 0, 0, H1>,
                         cudaFuncAttributeMaxDynamicSharedMemorySize, SMEM_BYTES);
    cudaFuncSetAttribute(gemm_mma<H1, 1, 0, H2>,
                         cudaFuncAttributeMaxDynamicSharedMemorySize, SMEM_BYTES);
    cudaFuncSetAttribute(gemm_mma<H2, 1, 1, H3>,
                         cudaFuncAttributeMaxDynamicSharedMemorySize, SMEM_BYTES);

    float* Y1; cudaGetSymbolAddress((void**)&Y1, g_Y1);
    float* Y2; cudaGetSymbolAddress((void**)&Y2, g_Y2);

    k_prefix<<<1, 32>>>(num);

    gemm_mma<D_IN, 0, 0, H1><<<dim3(E_TOT / 128, H1 / 128), 256, SMEM_BYTES>>>(
        feat, nodes, gfeat, ind, W1, b1, Y1);

    gemm_mma<H1, 1, 0, H2><<<dim3(E_TOT / 128, H2 / 128), 256, SMEM_BYTES>>>(
        Y1, nullptr, nullptr, nullptr, W2, b2, Y2);

    gemm_mma<H2, 1, 1, H3><<<dim3(E_TOT / 128, H3 / 128), 256, SMEM_BYTES>>>(
        Y2, nullptr, nullptr, nullptr, W3, b3, Y1);

    k_ln<<<E_TOT / 8, 256>>>(Y1, gamma, beta, out);
}